// round 1
// baseline (speedup 1.0000x reference)
#include <cuda_runtime.h>
#include <math.h>

#define BS_TOK 16384
#define DIM    1024
#define NEXP   8
#define KTOK   2048
#define DDIM   4096

// ---------------- scratch (device globals; allocation-free rule) ----------
__device__ float g_norm[(size_t)BS_TOK * DIM];      // 64 MiB
__device__ float g_scores[(size_t)BS_TOK * NEXP];
__device__ int   g_kidx[NEXP * KTOK];
__device__ float g_kscore[NEXP * KTOK];
__device__ float g_mask[(size_t)BS_TOK * NEXP];
__device__ float g_c1[(size_t)BS_TOK * DIM];        // 64 MiB
__device__ float g_h1[(size_t)NEXP * KTOK * DDIM];  // 256 MiB
__device__ float g_lacc;

// ---------------- helpers --------------------------------------------------
__device__ __forceinline__ float warpSum(float v) {
#pragma unroll
    for (int o = 16; o; o >>= 1) v += __shfl_xor_sync(0xffffffffu, v, o);
    return v;
}

__device__ __forceinline__ float gelu_tanh(float x) {
    float x3 = x * x * x;
    float t = tanhf(0.7978845608028654f * (x + 0.044715f * x3));
    return 0.5f * x * (1.f + t);
}

// ---------------- 1: init: out = x copy, zero loss accum --------------------
__global__ void init_kernel(const float* __restrict__ x, float* __restrict__ out, long n4) {
    long i = (long)blockIdx.x * blockDim.x + threadIdx.x;
    if (i == 0) g_lacc = 0.f;
    const float4* xs = (const float4*)x;
    float4* os = (float4*)out;
    long stride = (long)gridDim.x * blockDim.x;
    for (; i < n4; i += stride) os[i] = xs[i];
}

// ---------------- 2: fused LayerNorm + gate scores --------------------------
__global__ __launch_bounds__(256) void ln_gate_kernel(
    const float* __restrict__ x, const float* __restrict__ g,
    const float* __restrict__ bparam, const float* __restrict__ gW)
{
    int row = blockIdx.x;
    int t = threadIdx.x, lane = t & 31, w = t >> 5;
    const float4* xr = (const float4*)(x + (size_t)row * DIM);
    float4 v = xr[t];

    __shared__ float red[8];
    __shared__ float sMean, sRstd;

    float s = v.x + v.y + v.z + v.w;
    s = warpSum(s);
    if (lane == 0) red[w] = s;
    __syncthreads();
    if (t == 0) {
        float tot = 0;
#pragma unroll
        for (int i = 0; i < 8; i++) tot += red[i];
        sMean = tot * (1.f / DIM);
    }
    __syncthreads();
    float mu = sMean;
    float d0 = v.x - mu, d1 = v.y - mu, d2 = v.z - mu, d3 = v.w - mu;
    float s2 = d0 * d0 + d1 * d1 + d2 * d2 + d3 * d3;
    s2 = warpSum(s2);
    __syncthreads();
    if (lane == 0) red[w] = s2;
    __syncthreads();
    if (t == 0) {
        float tot = 0;
#pragma unroll
        for (int i = 0; i < 8; i++) tot += red[i];
        sRstd = rsqrtf(tot * (1.f / DIM) + 1e-5f);
    }
    __syncthreads();
    float rstd = sRstd;

    float4 gv = ((const float4*)g)[t];
    float4 bv = ((const float4*)bparam)[t];
    float4 nv;
    nv.x = d0 * rstd * gv.x + bv.x;
    nv.y = d1 * rstd * gv.y + bv.y;
    nv.z = d2 * rstd * gv.z + bv.z;
    nv.w = d3 * rstd * gv.w + bv.w;
    ((float4*)(g_norm + (size_t)row * DIM))[t] = nv;

    float acc[NEXP];
#pragma unroll
    for (int n = 0; n < NEXP; n++) {
        float4 wv = ((const float4*)(gW + (size_t)n * DIM))[t];
        float a = nv.x * wv.x + nv.y * wv.y + nv.z * wv.z + nv.w * wv.w;
        acc[n] = warpSum(a);
    }
    __shared__ float sacc[8][NEXP];
    if (lane == 0) {
#pragma unroll
        for (int n = 0; n < NEXP; n++) sacc[w][n] = acc[n];
    }
    __syncthreads();
    if (t < NEXP) {
        float tot = 0;
#pragma unroll
        for (int i = 0; i < 8; i++) tot += sacc[i][t];
        g_scores[(size_t)row * NEXP + t] = 0.5f * (tanhf(tot) + 1.f);
    }
}

// ---------------- 3: per-expert top-k via radix select ----------------------
// Exact semantics of argsort(-scores)[:k]: top-k values, ties broken by
// smallest original index (scores are positive floats -> bit pattern ordered).
__global__ __launch_bounds__(256) void topk_kernel() {
    int n = blockIdx.x;
    __shared__ unsigned int hist[256];
    __shared__ unsigned int s_prefix;
    __shared__ int s_remk;
    __shared__ int s_cnt;

    for (int i = threadIdx.x; i < BS_TOK; i += blockDim.x)
        g_mask[(size_t)i * NEXP + n] = 0.f;
    if (threadIdx.x == 0) s_cnt = 0;
    __syncthreads();

    unsigned int prefix = 0;
    int remk = KTOK;
    for (int pass = 0; pass < 4; pass++) {
        int shift = 24 - 8 * pass;
        for (int i = threadIdx.x; i < 256; i += blockDim.x) hist[i] = 0;
        __syncthreads();
        unsigned int himask = (pass == 0) ? 0u : (0xFFFFFFFFu << (shift + 8));
        unsigned int hipref = (pass == 0) ? 0u : (prefix << (shift + 8));
        for (int i = threadIdx.x; i < BS_TOK; i += blockDim.x) {
            unsigned int key = __float_as_uint(g_scores[(size_t)i * NEXP + n]);
            if ((key & himask) == hipref) atomicAdd(&hist[(key >> shift) & 255u], 1u);
        }
        __syncthreads();
        if (threadIdx.x == 0) {
            int cum = 0;
            for (int b = 255; b >= 0; b--) {
                int c = (int)hist[b];
                if (cum + c >= remk) {
                    s_prefix = (prefix << 8) | (unsigned)b;
                    s_remk = remk - cum;
                    break;
                }
                cum += c;
            }
        }
        __syncthreads();
        prefix = s_prefix;
        remk = s_remk;
        __syncthreads();
    }
    unsigned int kth = prefix;

    for (int i = threadIdx.x; i < BS_TOK; i += blockDim.x) {
        unsigned int key = __float_as_uint(g_scores[(size_t)i * NEXP + n]);
        bool sel = false;
        if (key > kth) sel = true;
        else if (key == kth) {
            // rank among equal keys by index (stable-sort tie break); ties are
            // essentially nonexistent so this scan almost never runs.
            int rank = 0;
            for (int j = 0; j < i; j++)
                if (__float_as_uint(g_scores[(size_t)j * NEXP + n]) == kth) rank++;
            sel = (rank < remk);
        }
        if (sel) {
            int slot = atomicAdd(&s_cnt, 1);
            g_kidx[n * KTOK + slot] = i;
            g_kscore[n * KTOK + slot] = __uint_as_float(key);
            g_mask[(size_t)i * NEXP + n] = 1.f;
        }
    }
}

// ---------------- shared SGEMM body: C[M,N] = A[M,K] @ B[N,K]^T --------------
// 128x128 block tile, BK=8, 256 threads, 8x8 per thread. All dims are
// multiples of 128/8 here, so no bounds checks.
template <int GATHER_A, int GELU, int SCATTER>
__device__ __forceinline__ void sgemm_body(
    const float* __restrict__ A, const float* __restrict__ B,
    const float* __restrict__ bias, float* __restrict__ C,
    int M, int N, int K,
    const int* __restrict__ gidx, const float* __restrict__ ksc,
    float* __restrict__ scOut)
{
    __shared__ __align__(16) float As[8][128];
    __shared__ __align__(16) float Bs[8][128];

    int tid = threadIdx.x;
    int brow = blockIdx.y * 128, bcol = blockIdx.x * 128;
    int lr = tid >> 1;
    int lc = (tid & 1) * 4;

    int am = brow + lr;
    int arow = GATHER_A ? gidx[am] : am;
    const float* Ap = A + (size_t)arow * K + lc;
    const float* Bp = B + (size_t)(bcol + lr) * K + lc;

    float acc[8][8];
#pragma unroll
    for (int i = 0; i < 8; i++)
#pragma unroll
        for (int j = 0; j < 8; j++) acc[i][j] = 0.f;

    int ty = tid >> 4, tx = tid & 15;

    for (int k0 = 0; k0 < K; k0 += 8) {
        float4 av = *(const float4*)(Ap + k0);
        float4 bv = *(const float4*)(Bp + k0);
        __syncthreads();
        As[lc + 0][lr] = av.x; As[lc + 1][lr] = av.y;
        As[lc + 2][lr] = av.z; As[lc + 3][lr] = av.w;
        Bs[lc + 0][lr] = bv.x; Bs[lc + 1][lr] = bv.y;
        Bs[lc + 2][lr] = bv.z; Bs[lc + 3][lr] = bv.w;
        __syncthreads();
#pragma unroll
        for (int kk = 0; kk < 8; kk++) {
            float ra[8], rb[8];
            *(float4*)(ra)     = *(const float4*)&As[kk][ty * 8];
            *(float4*)(ra + 4) = *(const float4*)&As[kk][ty * 8 + 4];
            *(float4*)(rb)     = *(const float4*)&Bs[kk][tx * 8];
            *(float4*)(rb + 4) = *(const float4*)&Bs[kk][tx * 8 + 4];
#pragma unroll
            for (int i = 0; i < 8; i++)
#pragma unroll
                for (int j = 0; j < 8; j++)
                    acc[i][j] = fmaf(ra[i], rb[j], acc[i][j]);
        }
    }

#pragma unroll
    for (int i = 0; i < 8; i++) {
        int m = brow + ty * 8 + i;
        int orow = m;
        float scale = 1.f;
        if (SCATTER) { orow = gidx[m]; scale = ksc[m]; }
#pragma unroll
        for (int j = 0; j < 8; j++) {
            int ncol = bcol + tx * 8 + j;
            float v = acc[i][j] + bias[ncol];
            if (GELU) v = gelu_tanh(v);
            if (SCATTER)
                atomicAdd(&scOut[(size_t)orow * N + ncol], v * scale);
            else
                C[(size_t)m * N + ncol] = v;
        }
    }
}

// ---------------- 4: cap path GEMM: g_c1 = gelu(g_norm @ cp_W1^T + b1) -------
__global__ __launch_bounds__(256) void cap_gemm_kernel(
    const float* __restrict__ W1, const float* __restrict__ b1)
{
    sgemm_body<0, 1, 0>(g_norm, W1, b1, g_c1, BS_TOK, DIM, DIM,
                        nullptr, nullptr, nullptr);
}

// ---------------- 5: logits + softplus loss reduction -----------------------
__global__ __launch_bounds__(256) void loss_kernel(
    const float* __restrict__ W2, const float* __restrict__ b2)
{
    int lane = threadIdx.x & 31, w = threadIdx.x >> 5;
    int row = blockIdx.x * 8 + w;
    const float* r = g_c1 + (size_t)row * DIM;
    float a[NEXP];
#pragma unroll
    for (int n = 0; n < NEXP; n++) a[n] = 0.f;
    for (int d = lane; d < DIM; d += 32) {
        float v = r[d];
#pragma unroll
        for (int n = 0; n < NEXP; n++) a[n] += v * W2[n * DIM + d];
    }
#pragma unroll
    for (int n = 0; n < NEXP; n++) a[n] = warpSum(a[n]);

    __shared__ float wpart[8];
    if (lane == 0) {
        float part = 0.f;
#pragma unroll
        for (int n = 0; n < NEXP; n++) {
            float l = a[n] + b2[n];
            float sp = fmaxf(l, 0.f) + log1pf(expf(-fabsf(l)));
            part += sp - l * g_mask[(size_t)row * NEXP + n];
        }
        wpart[w] = part;
    }
    __syncthreads();
    if (threadIdx.x == 0) {
        float s = 0.f;
#pragma unroll
        for (int i = 0; i < 8; i++) s += wpart[i];
        atomicAdd(&g_lacc, s);
    }
}

// ---------------- 6: expert fc1 (gather A rows) ------------------------------
__global__ __launch_bounds__(256) void fc1_kernel(
    const float* __restrict__ fc1s, const float* __restrict__ b1s)
{
    int z = blockIdx.z;
    sgemm_body<1, 1, 0>(g_norm,
                        fc1s + (size_t)z * DDIM * DIM,
                        b1s + (size_t)z * DDIM,
                        g_h1 + (size_t)z * KTOK * DDIM,
                        KTOK, DDIM, DIM,
                        g_kidx + z * KTOK, nullptr, nullptr);
}

// ---------------- 7: expert fc2 + scale + scatter-add ------------------------
__global__ __launch_bounds__(256) void fc2_kernel(
    const float* __restrict__ fc2s, const float* __restrict__ b2s,
    float* __restrict__ out)
{
    int z = blockIdx.z;
    sgemm_body<0, 0, 1>(g_h1 + (size_t)z * KTOK * DDIM,
                        fc2s + (size_t)z * DIM * DDIM,
                        b2s + (size_t)z * DIM,
                        nullptr, KTOK, DIM, DDIM,
                        g_kidx + z * KTOK, g_kscore + z * KTOK, out);
}

// ---------------- 8: finalize scalar loss ------------------------------------
__global__ void finalize_kernel(float* __restrict__ dst) {
    *dst = g_lacc * (1.f / ((float)BS_TOK * (float)NEXP));
}

// ---------------- launch -----------------------------------------------------
extern "C" void kernel_launch(void* const* d_in, const int* in_sizes, int n_in,
                              void* d_out, int out_size) {
    const float* x     = (const float*)d_in[0];
    const float* ln_g  = (const float*)d_in[1];
    const float* ln_b  = (const float*)d_in[2];
    const float* gateW = (const float*)d_in[3];
    const float* cpW1  = (const float*)d_in[4];
    const float* cpb1  = (const float*)d_in[5];
    const float* cpW2  = (const float*)d_in[6];
    const float* cpb2  = (const float*)d_in[7];
    const float* fc1s  = (const float*)d_in[8];
    const float* b1s   = (const float*)d_in[9];
    const float* fc2s  = (const float*)d_in[10];
    const float* b2s   = (const float*)d_in[11];
    float* out = (float*)d_out;

    // 1. out = x, zero loss accumulator
    init_kernel<<<4096, 256>>>(x, out, (long)BS_TOK * DIM / 4);
    // 2. layernorm + gate scores
    ln_gate_kernel<<<BS_TOK, 256>>>(x, ln_g, ln_b, gateW);
    // 3. per-expert top-k
    topk_kernel<<<NEXP, 256>>>();
    // 4. capacity-path GEMM (gelu)
    cap_gemm_kernel<<<dim3(DIM / 128, BS_TOK / 128, 1), 256>>>(cpW1, cpb1);
    // 5. logits + loss reduction
    loss_kernel<<<BS_TOK / 8, 256>>>(cpW2, cpb2);
    // 6. expert fc1 (gathered)
    fc1_kernel<<<dim3(DDIM / 128, KTOK / 128, NEXP), 256>>>(fc1s, b1s);
    // 7. expert fc2 + scaled scatter-add into out
    fc2_kernel<<<dim3(DIM / 128, KTOK / 128, NEXP), 256>>>(fc2s, b2s, out);
    // 8. scalar cap_loss at the tail of d_out
    finalize_kernel<<<1, 1>>>(out + (out_size - 1));
}

// round 3
// speedup vs baseline: 2.2316x; 2.2316x over previous
#include <cuda_runtime.h>
#include <math.h>
#include <stdint.h>

#define BS_TOK 16384
#define DIM    1024
#define NEXP   8
#define KTOK   2048
#define DDIM   4096

// GEMM tiling
#define BM 128
#define BN 128
#define BK 16
#define PAD 8

// ---------------- scratch (device globals; allocation-free rule) ----------
__device__ float g_norm[(size_t)BS_TOK * DIM];      // 64 MiB
__device__ float g_scores[(size_t)BS_TOK * NEXP];
__device__ int   g_kidx[NEXP * KTOK];
__device__ float g_kscore[NEXP * KTOK];
__device__ float g_mask[(size_t)BS_TOK * NEXP];
__device__ float g_c1[(size_t)BS_TOK * DIM];        // 64 MiB
__device__ float g_h1[(size_t)NEXP * KTOK * DDIM];  // 256 MiB
__device__ float g_lacc;

// ---------------- helpers --------------------------------------------------
__device__ __forceinline__ float warpSum(float v) {
#pragma unroll
    for (int o = 16; o; o >>= 1) v += __shfl_xor_sync(0xffffffffu, v, o);
    return v;
}

__device__ __forceinline__ float gelu_tanh(float x) {
    float x3 = x * x * x;
    float t = tanhf(0.7978845608028654f * (x + 0.044715f * x3));
    return 0.5f * x * (1.f + t);
}

__device__ __forceinline__ uint32_t f2tf32(float x) {
    uint32_t u;
    asm("cvt.rna.tf32.f32 %0, %1;" : "=r"(u) : "f"(x));
    return u;
}

__device__ __forceinline__ void mma_tf32(float* c, const uint32_t* a, const uint32_t* b) {
    asm volatile(
        "mma.sync.aligned.m16n8k8.row.col.f32.tf32.tf32.f32 "
        "{%0,%1,%2,%3}, {%4,%5,%6,%7}, {%8,%9}, {%0,%1,%2,%3};"
        : "+f"(c[0]), "+f"(c[1]), "+f"(c[2]), "+f"(c[3])
        : "r"(a[0]), "r"(a[1]), "r"(a[2]), "r"(a[3]), "r"(b[0]), "r"(b[1]));
}

// ---------------- tensor-core tf32 GEMM body --------------------------------
// C[M,N] = A[M,K] @ B[N,K]^T  (both K-major).
// BM=BN=128, BK=16, 256 threads = 8 warps (2 x 4), warp tile 64x32.
template <int GATHER_A, int GELU, int SCATTER>
__device__ __forceinline__ void tc_gemm_body(
    const float* __restrict__ A, int K,
    const float* __restrict__ B,
    const float* __restrict__ bias,
    float* __restrict__ C, int N,
    const int* __restrict__ gidx, const float* __restrict__ ksc,
    float* __restrict__ scOut)
{
    __shared__ float As[2][BK][BM + PAD];
    __shared__ float Bs[2][BK][BN + PAD];
    __shared__ int s_rows[BM];

    const int tid = threadIdx.x;
    const int wid = tid >> 5, lane = tid & 31;
    const int gid = lane >> 2, tig = lane & 3;
    const int warp_m = (wid >> 2) * 64;
    const int warp_n = (wid & 3) * 32;
    const int brow = blockIdx.y * BM;
    const int bcol = blockIdx.x * BN;

    if (GATHER_A) {
        if (tid < BM) s_rows[tid] = gidx[brow + tid];
        __syncthreads();
    }

    float acc[4][4][4];
#pragma unroll
    for (int i = 0; i < 4; i++)
#pragma unroll
        for (int j = 0; j < 4; j++)
#pragma unroll
            for (int q = 0; q < 4; q++) acc[i][j][q] = 0.f;

    // per-thread global-load coords: f = i*256 + tid, row = f>>2, c4 = (f&3)*4
    const int r0 = tid >> 2;            // i=0 -> rows 0..63
    const int r1 = 64 + (tid >> 2);     // i=1 -> rows 64..127
    const int c4 = (tid & 3) * 4;
    const int ar0 = GATHER_A ? s_rows[r0] : (brow + r0);
    const int ar1 = GATHER_A ? s_rows[r1] : (brow + r1);
    const float* Ap0 = A + (size_t)ar0 * K + c4;
    const float* Ap1 = A + (size_t)ar1 * K + c4;
    const float* Bp0 = B + (size_t)(bcol + r0) * K + c4;
    const float* Bp1 = B + (size_t)(bcol + r1) * K + c4;

    const int nck = K / BK;

    float4 fa0, fa1, fb0, fb1;
    // prologue: load + store chunk 0
    fa0 = *(const float4*)(Ap0);
    fa1 = *(const float4*)(Ap1);
    fb0 = *(const float4*)(Bp0);
    fb1 = *(const float4*)(Bp1);
    {
        float* a0 = &As[0][c4][r0];
        float* a1 = &As[0][c4][r1];
        float* b0 = &Bs[0][c4][r0];
        float* b1 = &Bs[0][c4][r1];
        const int st = BM + PAD;
        a0[0] = __uint_as_float(f2tf32(fa0.x)); a0[st] = __uint_as_float(f2tf32(fa0.y));
        a0[2*st] = __uint_as_float(f2tf32(fa0.z)); a0[3*st] = __uint_as_float(f2tf32(fa0.w));
        a1[0] = __uint_as_float(f2tf32(fa1.x)); a1[st] = __uint_as_float(f2tf32(fa1.y));
        a1[2*st] = __uint_as_float(f2tf32(fa1.z)); a1[3*st] = __uint_as_float(f2tf32(fa1.w));
        b0[0] = __uint_as_float(f2tf32(fb0.x)); b0[st] = __uint_as_float(f2tf32(fb0.y));
        b0[2*st] = __uint_as_float(f2tf32(fb0.z)); b0[3*st] = __uint_as_float(f2tf32(fb0.w));
        b1[0] = __uint_as_float(f2tf32(fb1.x)); b1[st] = __uint_as_float(f2tf32(fb1.y));
        b1[2*st] = __uint_as_float(f2tf32(fb1.z)); b1[3*st] = __uint_as_float(f2tf32(fb1.w));
    }
    __syncthreads();

    for (int c = 0; c < nck; ++c) {
        const int buf = c & 1;
        const bool more = (c + 1 < nck);
        if (more) {
            int k0 = (c + 1) * BK;
            fa0 = *(const float4*)(Ap0 + k0);
            fa1 = *(const float4*)(Ap1 + k0);
            fb0 = *(const float4*)(Bp0 + k0);
            fb1 = *(const float4*)(Bp1 + k0);
        }

        // compute chunk c (2 k8-steps) — hides the LDGs above
#pragma unroll
        for (int kk = 0; kk < 2; kk++) {
            uint32_t afr[4][4], bfr[4][2];
            const int kb = kk * 8;
#pragma unroll
            for (int i = 0; i < 4; i++) {
                int m = warp_m + i * 16 + gid;
                afr[i][0] = __float_as_uint(As[buf][kb + tig][m]);
                afr[i][1] = __float_as_uint(As[buf][kb + tig][m + 8]);
                afr[i][2] = __float_as_uint(As[buf][kb + tig + 4][m]);
                afr[i][3] = __float_as_uint(As[buf][kb + tig + 4][m + 8]);
            }
#pragma unroll
            for (int j = 0; j < 4; j++) {
                int n = warp_n + j * 8 + gid;
                bfr[j][0] = __float_as_uint(Bs[buf][kb + tig][n]);
                bfr[j][1] = __float_as_uint(Bs[buf][kb + tig + 4][n]);
            }
#pragma unroll
            for (int i = 0; i < 4; i++)
#pragma unroll
                for (int j = 0; j < 4; j++)
                    mma_tf32(acc[i][j], afr[i], bfr[j]);
        }

        if (more) {
            __syncthreads();
            const int nb = buf ^ 1;
            float* a0 = &As[nb][c4][r0];
            float* a1 = &As[nb][c4][r1];
            float* b0 = &Bs[nb][c4][r0];
            float* b1 = &Bs[nb][c4][r1];
            const int st = BM + PAD;
            a0[0] = __uint_as_float(f2tf32(fa0.x)); a0[st] = __uint_as_float(f2tf32(fa0.y));
            a0[2*st] = __uint_as_float(f2tf32(fa0.z)); a0[3*st] = __uint_as_float(f2tf32(fa0.w));
            a1[0] = __uint_as_float(f2tf32(fa1.x)); a1[st] = __uint_as_float(f2tf32(fa1.y));
            a1[2*st] = __uint_as_float(f2tf32(fa1.z)); a1[3*st] = __uint_as_float(f2tf32(fa1.w));
            b0[0] = __uint_as_float(f2tf32(fb0.x)); b0[st] = __uint_as_float(f2tf32(fb0.y));
            b0[2*st] = __uint_as_float(f2tf32(fb0.z)); b0[3*st] = __uint_as_float(f2tf32(fb0.w));
            b1[0] = __uint_as_float(f2tf32(fb1.x)); b1[st] = __uint_as_float(f2tf32(fb1.y));
            b1[2*st] = __uint_as_float(f2tf32(fb1.z)); b1[3*st] = __uint_as_float(f2tf32(fb1.w));
            __syncthreads();
        }
    }

    // epilogue
#pragma unroll
    for (int i = 0; i < 4; i++) {
        int mrow0 = brow + warp_m + i * 16 + gid;
        int mrow1 = mrow0 + 8;
        int or0 = mrow0, or1 = mrow1;
        float sc0 = 1.f, sc1 = 1.f;
        if (SCATTER) {
            or0 = gidx[mrow0]; sc0 = ksc[mrow0];
            or1 = gidx[mrow1]; sc1 = ksc[mrow1];
        }
#pragma unroll
        for (int j = 0; j < 4; j++) {
            int ncol = bcol + warp_n + j * 8 + tig * 2;
            float bi0 = bias[ncol - bcol + (bcol)];           // bias indexed by global col
            bi0 = bias[warp_n + j * 8 + tig * 2 + bcol];
            float bi1 = bias[warp_n + j * 8 + tig * 2 + 1 + bcol];
            float v00 = acc[i][j][0] + bi0;
            float v01 = acc[i][j][1] + bi1;
            float v10 = acc[i][j][2] + bi0;
            float v11 = acc[i][j][3] + bi1;
            if (GELU) {
                v00 = gelu_tanh(v00); v01 = gelu_tanh(v01);
                v10 = gelu_tanh(v10); v11 = gelu_tanh(v11);
            }
            if (SCATTER) {
                atomicAdd(&scOut[(size_t)or0 * N + ncol],     v00 * sc0);
                atomicAdd(&scOut[(size_t)or0 * N + ncol + 1], v01 * sc0);
                atomicAdd(&scOut[(size_t)or1 * N + ncol],     v10 * sc1);
                atomicAdd(&scOut[(size_t)or1 * N + ncol + 1], v11 * sc1);
            } else {
                *(float2*)&C[(size_t)mrow0 * N + ncol] = make_float2(v00, v01);
                *(float2*)&C[(size_t)mrow1 * N + ncol] = make_float2(v10, v11);
            }
        }
    }
}

// ---------------- GEMM wrappers ----------------------------------------------
__global__ __launch_bounds__(256) void cap_tc(const float* __restrict__ W1,
                                              const float* __restrict__ b1) {
    tc_gemm_body<0, 1, 0>(g_norm, DIM, W1, b1, g_c1, DIM, nullptr, nullptr, nullptr);
}

__global__ __launch_bounds__(256) void fc1_tc(const float* __restrict__ fc1s,
                                              const float* __restrict__ b1s) {
    int z = blockIdx.z;
    tc_gemm_body<1, 1, 0>(g_norm, DIM,
                          fc1s + (size_t)z * DDIM * DIM,
                          b1s + (size_t)z * DDIM,
                          g_h1 + (size_t)z * KTOK * DDIM, DDIM,
                          g_kidx + z * KTOK, nullptr, nullptr);
}

__global__ __launch_bounds__(256) void fc2_tc(const float* __restrict__ fc2s,
                                              const float* __restrict__ b2s,
                                              float* __restrict__ out) {
    int z = blockIdx.z;
    tc_gemm_body<0, 0, 1>(g_h1 + (size_t)z * KTOK * DDIM, DDIM,
                          fc2s + (size_t)z * DIM * DDIM,
                          b2s + (size_t)z * DIM,
                          nullptr, DIM,
                          g_kidx + z * KTOK, g_kscore + z * KTOK, out);
}

// ---------------- 1: init ------------------------------------------------------
__global__ void init_kernel(const float* __restrict__ x, float* __restrict__ out, long n4) {
    long i = (long)blockIdx.x * blockDim.x + threadIdx.x;
    if (i == 0) g_lacc = 0.f;
    const float4* xs = (const float4*)x;
    float4* os = (float4*)out;
    long stride = (long)gridDim.x * blockDim.x;
    for (; i < n4; i += stride) os[i] = xs[i];
}

// ---------------- 2: fused LayerNorm + gate scores -----------------------------
__global__ __launch_bounds__(256) void ln_gate_kernel(
    const float* __restrict__ x, const float* __restrict__ g,
    const float* __restrict__ bparam, const float* __restrict__ gW)
{
    int row = blockIdx.x;
    int t = threadIdx.x, lane = t & 31, w = t >> 5;
    const float4* xr = (const float4*)(x + (size_t)row * DIM);
    float4 v = xr[t];

    __shared__ float red[8];
    __shared__ float sMean, sRstd;

    float s = v.x + v.y + v.z + v.w;
    s = warpSum(s);
    if (lane == 0) red[w] = s;
    __syncthreads();
    if (t == 0) {
        float tot = 0;
#pragma unroll
        for (int i = 0; i < 8; i++) tot += red[i];
        sMean = tot * (1.f / DIM);
    }
    __syncthreads();
    float mu = sMean;
    float d0 = v.x - mu, d1 = v.y - mu, d2 = v.z - mu, d3 = v.w - mu;
    float s2 = d0 * d0 + d1 * d1 + d2 * d2 + d3 * d3;
    s2 = warpSum(s2);
    __syncthreads();
    if (lane == 0) red[w] = s2;
    __syncthreads();
    if (t == 0) {
        float tot = 0;
#pragma unroll
        for (int i = 0; i < 8; i++) tot += red[i];
        sRstd = rsqrtf(tot * (1.f / DIM) + 1e-5f);
    }
    __syncthreads();
    float rstd = sRstd;

    float4 gv = ((const float4*)g)[t];
    float4 bv = ((const float4*)bparam)[t];
    float4 nv;
    nv.x = d0 * rstd * gv.x + bv.x;
    nv.y = d1 * rstd * gv.y + bv.y;
    nv.z = d2 * rstd * gv.z + bv.z;
    nv.w = d3 * rstd * gv.w + bv.w;
    ((float4*)(g_norm + (size_t)row * DIM))[t] = nv;

    float acc[NEXP];
#pragma unroll
    for (int n = 0; n < NEXP; n++) {
        float4 wv = ((const float4*)(gW + (size_t)n * DIM))[t];
        float a = nv.x * wv.x + nv.y * wv.y + nv.z * wv.z + nv.w * wv.w;
        acc[n] = warpSum(a);
    }
    __shared__ float sacc[8][NEXP];
    if (lane == 0) {
#pragma unroll
        for (int n = 0; n < NEXP; n++) sacc[w][n] = acc[n];
    }
    __syncthreads();
    if (t < NEXP) {
        float tot = 0;
#pragma unroll
        for (int i = 0; i < 8; i++) tot += sacc[i][t];
        g_scores[(size_t)row * NEXP + t] = 0.5f * (tanhf(tot) + 1.f);
    }
}

// ---------------- 3: per-expert top-k via radix select -------------------------
__global__ __launch_bounds__(256) void topk_kernel() {
    int n = blockIdx.x;
    __shared__ unsigned int hist[256];
    __shared__ unsigned int s_prefix;
    __shared__ int s_remk;
    __shared__ int s_cnt;

    for (int i = threadIdx.x; i < BS_TOK; i += blockDim.x)
        g_mask[(size_t)i * NEXP + n] = 0.f;
    if (threadIdx.x == 0) s_cnt = 0;
    __syncthreads();

    unsigned int prefix = 0;
    int remk = KTOK;
    for (int pass = 0; pass < 4; pass++) {
        int shift = 24 - 8 * pass;
        for (int i = threadIdx.x; i < 256; i += blockDim.x) hist[i] = 0;
        __syncthreads();
        unsigned int himask = (pass == 0) ? 0u : (0xFFFFFFFFu << (shift + 8));
        unsigned int hipref = (pass == 0) ? 0u : (prefix << (shift + 8));
        for (int i = threadIdx.x; i < BS_TOK; i += blockDim.x) {
            unsigned int key = __float_as_uint(g_scores[(size_t)i * NEXP + n]);
            if ((key & himask) == hipref) atomicAdd(&hist[(key >> shift) & 255u], 1u);
        }
        __syncthreads();
        if (threadIdx.x == 0) {
            int cum = 0;
            for (int b = 255; b >= 0; b--) {
                int c = (int)hist[b];
                if (cum + c >= remk) {
                    s_prefix = (prefix << 8) | (unsigned)b;
                    s_remk = remk - cum;
                    break;
                }
                cum += c;
            }
        }
        __syncthreads();
        prefix = s_prefix;
        remk = s_remk;
        __syncthreads();
    }
    unsigned int kth = prefix;

    for (int i = threadIdx.x; i < BS_TOK; i += blockDim.x) {
        unsigned int key = __float_as_uint(g_scores[(size_t)i * NEXP + n]);
        bool sel = false;
        if (key > kth) sel = true;
        else if (key == kth) {
            int rank = 0;
            for (int j = 0; j < i; j++)
                if (__float_as_uint(g_scores[(size_t)j * NEXP + n]) == kth) rank++;
            sel = (rank < remk);
        }
        if (sel) {
            int slot = atomicAdd(&s_cnt, 1);
            g_kidx[n * KTOK + slot] = i;
            g_kscore[n * KTOK + slot] = __uint_as_float(key);
            g_mask[(size_t)i * NEXP + n] = 1.f;
        }
    }
}

// ---------------- 5: logits + softplus loss reduction --------------------------
__global__ __launch_bounds__(256) void loss_kernel(
    const float* __restrict__ W2, const float* __restrict__ b2)
{
    int lane = threadIdx.x & 31, w = threadIdx.x >> 5;
    int row = blockIdx.x * 8 + w;
    const float* r = g_c1 + (size_t)row * DIM;
    float a[NEXP];
#pragma unroll
    for (int n = 0; n < NEXP; n++) a[n] = 0.f;
    for (int d = lane; d < DIM; d += 32) {
        float v = r[d];
#pragma unroll
        for (int n = 0; n < NEXP; n++) a[n] += v * W2[n * DIM + d];
    }
#pragma unroll
    for (int n = 0; n < NEXP; n++) a[n] = warpSum(a[n]);

    __shared__ float wpart[8];
    if (lane == 0) {
        float part = 0.f;
#pragma unroll
        for (int n = 0; n < NEXP; n++) {
            float l = a[n] + b2[n];
            float sp = fmaxf(l, 0.f) + log1pf(expf(-fabsf(l)));
            part += sp - l * g_mask[(size_t)row * NEXP + n];
        }
        wpart[w] = part;
    }
    __syncthreads();
    if (threadIdx.x == 0) {
        float s = 0.f;
#pragma unroll
        for (int i = 0; i < 8; i++) s += wpart[i];
        atomicAdd(&g_lacc, s);
    }
}

// ---------------- 8: finalize scalar loss --------------------------------------
__global__ void finalize_kernel(float* __restrict__ dst) {
    *dst = g_lacc * (1.f / ((float)BS_TOK * (float)NEXP));
}

// ---------------- launch --------------------------------------------------------
extern "C" void kernel_launch(void* const* d_in, const int* in_sizes, int n_in,
                              void* d_out, int out_size) {
    const float* x     = (const float*)d_in[0];
    const float* ln_g  = (const float*)d_in[1];
    const float* ln_b  = (const float*)d_in[2];
    const float* gateW = (const float*)d_in[3];
    const float* cpW1  = (const float*)d_in[4];
    const float* cpb1  = (const float*)d_in[5];
    const float* cpW2  = (const float*)d_in[6];
    const float* cpb2  = (const float*)d_in[7];
    const float* fc1s  = (const float*)d_in[8];
    const float* b1s   = (const float*)d_in[9];
    const float* fc2s  = (const float*)d_in[10];
    const float* b2s   = (const float*)d_in[11];
    float* out = (float*)d_out;

    init_kernel<<<4096, 256>>>(x, out, (long)BS_TOK * DIM / 4);
    ln_gate_kernel<<<BS_TOK, 256>>>(x, ln_g, ln_b, gateW);
    topk_kernel<<<NEXP, 256>>>();
    cap_tc<<<dim3(DIM / BN, BS_TOK / BM, 1), 256>>>(cpW1, cpb1);
    loss_kernel<<<BS_TOK / 8, 256>>>(cpW2, cpb2);
    fc1_tc<<<dim3(DDIM / BN, KTOK / BM, NEXP), 256>>>(fc1s, b1s);
    fc2_tc<<<dim3(DIM / BN, KTOK / BM, NEXP), 256>>>(fc2s, b2s, out);
    finalize_kernel<<<1, 1>>>(out + (out_size - 1));
}